// round 3
// baseline (speedup 1.0000x reference)
#include <cuda_runtime.h>
#include <cstdint>

typedef unsigned long long u64;

// ---------- packed dual-fp32 helpers (Blackwell f32x2, PTX-only) ----------
__device__ __forceinline__ u64 pack2(float x, float y) {
    u64 r; asm("mov.b64 %0, {%1, %2};" : "=l"(r) : "f"(x), "f"(y)); return r;
}
__device__ __forceinline__ void unpack2(u64 v, float& x, float& y) {
    asm("mov.b64 {%0, %1}, %2;" : "=f"(x), "=f"(y) : "l"(v));
}
__device__ __forceinline__ u64 ffma2(u64 a, u64 b, u64 c) {
    u64 d; asm("fma.rn.f32x2 %0, %1, %2, %3;" : "=l"(d) : "l"(a), "l"(b), "l"(c)); return d;
}

// ---------- accurate fast transcendentals (MUFU EX2 + RCP, ~1e-6 rel) ----------
__device__ __forceinline__ float sigmoid_f(float x) {
    float e = __expf(-x);
    return __fdividef(1.0f, 1.0f + e);
}
__device__ __forceinline__ float tanh_f(float x) {
    float e = __expf(-2.0f * x);
    return __fdividef(1.0f - e, 1.0f + e);
}

struct __align__(16) SmemW {
    float W[24][64];   // rows 0..7 = Wx (8x64), rows 8..23 = Wh (16x64)
    float GB[64];      // bx + bh, 16B aligned (offset 6144)
    float WP[3][16];
    float BG[4][16];
    float WL[16];
    float BL;
};

// One 16-wide gate slice of g = [x|h] @ W + (bx+bh), packed f32x2 accumulation.
// joff in {0,16,32,48}; all indices compile-time after unroll -> registers only.
__device__ __forceinline__ void gemv16(const SmemW& s, const float (&in)[24],
                                       const int joff, float (&g)[16]) {
    u64 acc[8];
    const u64* gb2 = reinterpret_cast<const u64*>(s.GB);
#pragma unroll
    for (int p = 0; p < 8; ++p) acc[p] = gb2[(joff >> 1) + p];
#pragma unroll
    for (int k = 0; k < 24; ++k) {
        u64 a2 = pack2(in[k], in[k]);
        const ulonglong2* w = reinterpret_cast<const ulonglong2*>(&s.W[k][joff]);
#pragma unroll
        for (int q = 0; q < 4; ++q) {          // 4 x LDS.128 = 16 weights
            ulonglong2 wv = w[q];
            acc[2 * q]     = ffma2(a2, wv.x, acc[2 * q]);
            acc[2 * q + 1] = ffma2(a2, wv.y, acc[2 * q + 1]);
        }
    }
#pragma unroll
    for (int p = 0; p < 8; ++p) unpack2(acc[p], g[2 * p], g[2 * p + 1]);
}

__global__ __launch_bounds__(256, 2)
void gconvlstm_kernel(const float* __restrict__ x,
                      const float* __restrict__ h,
                      const float* __restrict__ c,
                      const float* __restrict__ Wx, const float* __restrict__ bx,
                      const float* __restrict__ Wh, const float* __restrict__ bh,
                      const float* __restrict__ w_peep,
                      const float* __restrict__ b_gates,
                      const float* __restrict__ W_lin,
                      const float* __restrict__ b_lin,
                      float* __restrict__ out,
                      float* __restrict__ h_new,
                      float* __restrict__ c_new,
                      int N)
{
    __shared__ SmemW s;

    // ---- cooperative weight staging (broadcast-read later) ----
    {
        const int t = threadIdx.x;
        float* Wflat = &s.W[0][0];
        for (int i = t; i < 8 * 64; i += blockDim.x)  Wflat[i]       = Wx[i];
        for (int i = t; i < 16 * 64; i += blockDim.x) Wflat[512 + i] = Wh[i];
        for (int i = t; i < 64; i += blockDim.x)      s.GB[i] = bx[i] + bh[i];
        for (int i = t; i < 48; i += blockDim.x)      (&s.WP[0][0])[i] = w_peep[i];
        for (int i = t; i < 64; i += blockDim.x)      (&s.BG[0][0])[i] = b_gates[i];
        for (int i = t; i < 16; i += blockDim.x)      s.WL[i] = W_lin[i];
        if (t == 0) s.BL = b_lin[0];
    }
    __syncthreads();

    const int n = blockIdx.x * blockDim.x + threadIdx.x;
    if (n >= N) return;

    // ---- load node inputs (fully coalesced float4) ----
    float in[24];
    {
        const float4* xv = reinterpret_cast<const float4*>(x + (size_t)n * 8);
        float4 a = xv[0], b = xv[1];
        in[0] = a.x; in[1] = a.y; in[2] = a.z; in[3] = a.w;
        in[4] = b.x; in[5] = b.y; in[6] = b.z; in[7] = b.w;
        const float4* hv = reinterpret_cast<const float4*>(h + (size_t)n * 16);
#pragma unroll
        for (int q = 0; q < 4; ++q) {
            float4 v = hv[q];
            in[8 + 4 * q + 0] = v.x; in[8 + 4 * q + 1] = v.y;
            in[8 + 4 * q + 2] = v.z; in[8 + 4 * q + 3] = v.w;
        }
    }
    float cc[16];
    {
        const float4* cv = reinterpret_cast<const float4*>(c + (size_t)n * 16);
#pragma unroll
        for (int q = 0; q < 4; ++q) {
            float4 v = cv[q];
            cc[4 * q + 0] = v.x; cc[4 * q + 1] = v.y;
            cc[4 * q + 2] = v.z; cc[4 * q + 3] = v.w;
        }
    }

    float g[16];

    // t = tanh(gc + bg2)            (gc slice: joff 32)
    float tg[16];
    gemv16(s, in, 32, g);
#pragma unroll
    for (int d = 0; d < 16; ++d) tg[d] = tanh_f(g[d] + s.BG[2][d]);

    // i = sigmoid(gi + wp0*c + bg0); it = i*t       (joff 0)
    float it[16];
    gemv16(s, in, 0, g);
#pragma unroll
    for (int d = 0; d < 16; ++d) {
        float iv = sigmoid_f(fmaf(s.WP[0][d], cc[d], g[d] + s.BG[0][d]));
        it[d] = iv * tg[d];
    }

    // f = sigmoid(gf + wp1*c + bg1); c_new = f*c + it     (joff 16)
    float cn[16];
    gemv16(s, in, 16, g);
#pragma unroll
    for (int d = 0; d < 16; ++d) {
        float fv = sigmoid_f(fmaf(s.WP[1][d], cc[d], g[d] + s.BG[1][d]));
        cn[d] = fmaf(fv, cc[d], it[d]);
    }

    // o = sigmoid(go + wp2*c_new + bg3); h_new = o*tanh(c_new)   (joff 48)
    float hn[16];
    gemv16(s, in, 48, g);
    float acc_out = s.BL;
#pragma unroll
    for (int d = 0; d < 16; ++d) {
        float ov = sigmoid_f(fmaf(s.WP[2][d], cn[d], g[d] + s.BG[3][d]));
        hn[d] = ov * tanh_f(cn[d]);
        acc_out = fmaf(fmaxf(hn[d], 0.0f), s.WL[d], acc_out);
    }

    // ---- stores (float4, coalesced) ----
    out[n] = acc_out;
    float4* hv = reinterpret_cast<float4*>(h_new + (size_t)n * 16);
    float4* cv = reinterpret_cast<float4*>(c_new + (size_t)n * 16);
#pragma unroll
    for (int q = 0; q < 4; ++q) {
        hv[q] = make_float4(hn[4 * q], hn[4 * q + 1], hn[4 * q + 2], hn[4 * q + 3]);
        cv[q] = make_float4(cn[4 * q], cn[4 * q + 1], cn[4 * q + 2], cn[4 * q + 3]);
    }
}

extern "C" void kernel_launch(void* const* d_in, const int* in_sizes, int n_in,
                              void* d_out, int out_size) {
    // metadata order: x, edge_index(unused), edge_attr(unused), h, c,
    //                 Wx, bx, Wh, bh, w_peep, b_gates, W_lin, b_lin
    const float* x  = (const float*)d_in[0];
    const float* h  = (const float*)d_in[3];
    const float* c  = (const float*)d_in[4];
    const float* Wx = (const float*)d_in[5];
    const float* bx = (const float*)d_in[6];
    const float* Wh = (const float*)d_in[7];
    const float* bh = (const float*)d_in[8];
    const float* wp = (const float*)d_in[9];
    const float* bg = (const float*)d_in[10];
    const float* wl = (const float*)d_in[11];
    const float* bl = (const float*)d_in[12];

    const int N = in_sizes[0] / 8;   // x is (N, 8)

    // outputs concatenated in reference return order: out[N], h_new[N*16], c_new[N*16]
    float* out = (float*)d_out;
    float* hn  = out + (size_t)N;
    float* cn  = hn + (size_t)N * 16;

    const int threads = 256;
    const int blocks = (N + threads - 1) / threads;
    gconvlstm_kernel<<<blocks, threads>>>(x, h, c, Wx, bx, Wh, bh, wp, bg, wl, bl,
                                          out, hn, cn, N);
}